// round 17
// baseline (speedup 1.0000x reference)
#include <cuda_runtime.h>
#include <cuda_fp16.h>
#include <cuda_bf16.h>

#define N_NODES 50000
#define DIM     128
#define N_EDGES 800000
#define TILE    512
#define TILES_PER_G 98          // ceil(50000/512)
#define N_TILES (2 * TILES_PER_G)
#define GM      128             // GEMM block M
#define NBLK    ((N_NODES + GM - 1) / GM)   // 391

// ---------------------------------------------------------------------------
// Scratch (device globals — no allocation allowed in kernel_launch)
// ---------------------------------------------------------------------------
__device__ int    g_cnt [2 * N_NODES];
__device__ int    g_offs[2 * (N_NODES + 1)];
__device__ int    g_cur [2 * N_NODES];
__device__ int    g_csr [2 * N_EDGES];
__device__ float  g_dinv[2 * N_NODES];
__device__ __half g_hsA [N_NODES * DIM];     // (x @ W) * dinv[row]  (fp16), graph 1
__device__ __half g_hsB [N_NODES * DIM];     // graph 2
__device__ __half g_h16A[N_NODES * DIM];     // hidden activations (fp16), graph 1
__device__ __half g_h16B[N_NODES * DIM];     // graph 2
__device__ int    g_tilesum [N_TILES];
// fp16 B fragments, nb-paired, m16n8k16 (same layout as R14-R16)
__device__ uint4  g_Bq[2 * 2048];

// ---------------------------------------------------------------------------
// helpers
// ---------------------------------------------------------------------------
__device__ __forceinline__ void mma16(float c[4], const unsigned a[4],
                                      unsigned b0, unsigned b1) {
    asm volatile(
        "mma.sync.aligned.m16n8k16.row.col.f32.f16.f16.f32 "
        "{%0,%1,%2,%3}, {%4,%5,%6,%7}, {%8,%9}, {%0,%1,%2,%3};"
        : "+f"(c[0]), "+f"(c[1]), "+f"(c[2]), "+f"(c[3])
        : "r"(a[0]), "r"(a[1]), "r"(a[2]), "r"(a[3]), "r"(b0), "r"(b1));
}

__device__ __forceinline__ void ldsm_x4(unsigned a[4], unsigned saddr) {
    asm volatile(
        "ldmatrix.sync.aligned.m8n8.x4.shared.b16 {%0,%1,%2,%3}, [%4];"
        : "=r"(a[0]), "=r"(a[1]), "=r"(a[2]), "=r"(a[3]) : "r"(saddr));
}

__device__ __forceinline__ unsigned pack_h2(float x, float y) {
    __half2 h = __floats2half2_rn(x, y);
    return *(unsigned*)&h;
}

// ---------------------------------------------------------------------------
// W pre-pack (fp16 fragment-native) FUSED with cnt zeroing.
// ---------------------------------------------------------------------------
__global__ void k_packw_zero(const float* __restrict__ W0, const float* __restrict__ W1) {
    int i = blockIdx.x * blockDim.x + threadIdx.x;
    if (i < 4096) {
        const float* W = (i < 2048) ? W0 : W1;
        int j   = i & 2047;
        int l4  = j & 3;
        int g   = (j >> 2) & 7;
        int nbp = (j >> 5) & 3;
        int wnh = (j >> 7) & 1;
        int ks  = (j >> 8) & 1;
        int kc  = j >> 9;
        int k0  = kc * 32 + ks * 16;
        int n0  = wnh * 64 + nbp * 16 + g;
        int n1  = n0 + 8;
        uint4 v;
        v.x = pack_h2(W[(k0 + l4 * 2)     * 128 + n0], W[(k0 + l4 * 2 + 1) * 128 + n0]);
        v.y = pack_h2(W[(k0 + 8 + l4 * 2) * 128 + n0], W[(k0 + 9 + l4 * 2) * 128 + n0]);
        v.z = pack_h2(W[(k0 + l4 * 2)     * 128 + n1], W[(k0 + l4 * 2 + 1) * 128 + n1]);
        v.w = pack_h2(W[(k0 + 8 + l4 * 2) * 128 + n1], W[(k0 + 9 + l4 * 2) * 128 + n1]);
        g_Bq[i] = v;
    }
    if (i < 2 * N_NODES) g_cnt[i] = 0;
}

// ---------------------------------------------------------------------------
// CSR build
// ---------------------------------------------------------------------------
__global__ void k_count2(const int* __restrict__ dst1, const int* __restrict__ dst2) {
    const int Q = N_EDGES / 4;
    int i = blockIdx.x * blockDim.x + threadIdx.x;
    int stride = gridDim.x * blockDim.x;
    for (; i < 2 * Q; i += stride) {
        int4 d;
        int base;
        if (i < Q) { d = __ldg((const int4*)dst1 + i); base = 0; }
        else       { d = __ldg((const int4*)dst2 + (i - Q)); base = N_NODES; }
        atomicAdd(&g_cnt[base + d.x], 1);
        atomicAdd(&g_cnt[base + d.y], 1);
        atomicAdd(&g_cnt[base + d.z], 1);
        atomicAdd(&g_cnt[base + d.w], 1);
    }
}

__global__ __launch_bounds__(TILE)
void k_blocksum() {
    int g  = blockIdx.x / TILES_PER_G;
    int lt = blockIdx.x % TILES_PER_G;
    int li = lt * TILE + threadIdx.x;
    int c = (li < N_NODES) ? g_cnt[g * N_NODES + li] : 0;

    int lane = threadIdx.x & 31, w = threadIdx.x >> 5;
    for (int o = 16; o > 0; o >>= 1) c += __shfl_down_sync(~0u, c, o);
    __shared__ int ws[TILE / 32];
    if (lane == 0) ws[w] = c;
    __syncthreads();
    if (threadIdx.x == 0) {
        int s = 0;
#pragma unroll
        for (int i = 0; i < TILE / 32; i++) s += ws[i];
        g_tilesum[blockIdx.x] = s;
    }
}

// Offsets with INLINE tile-base scan (replaces k_scanbase + k_offsets).
// Base = sum of tilesum for tiles before this one (masked 128-wide reduce).
__global__ __launch_bounds__(TILE)
void k_offsets() {
    int g  = blockIdx.x / TILES_PER_G;
    int lt = blockIdx.x % TILES_PER_G;
    int li = lt * TILE + threadIdx.x;
    int t  = threadIdx.x;

    __shared__ int red[128];
    if (t < 128)
        red[t] = (t < lt) ? g_tilesum[g * TILES_PER_G + t] : 0;   // lt <= 97 < 128
    __syncthreads();
#pragma unroll
    for (int o = 64; o > 0; o >>= 1) {
        if (t < o) red[t] += red[t + o];
        __syncthreads();
    }
    int base = red[0];

    int c = (li < N_NODES) ? g_cnt[g * N_NODES + li] : 0;
    int lane = t & 31, w = t >> 5;
    int v = c;
#pragma unroll
    for (int o = 1; o < 32; o <<= 1) {
        int x = __shfl_up_sync(~0u, v, o);
        if (lane >= o) v += x;
    }
    __shared__ int ws[TILE / 32];
    if (lane == 31) ws[w] = v;
    __syncthreads();
    if (w == 0 && lane < TILE / 32) {
        int s = ws[lane];
#pragma unroll
        for (int o = 1; o < TILE / 32; o <<= 1) {
            int x = __shfl_up_sync(0xffff, s, o);
            if (lane >= o) s += x;
        }
        ws[lane] = s;
    }
    __syncthreads();
    int excl = v - c + (w > 0 ? ws[w - 1] : 0);

    if (li < N_NODES) {
        int off = base + excl;
        g_offs[g * (N_NODES + 1) + li] = off;
        g_cur [g * N_NODES + li] = off;
        g_dinv[g * N_NODES + li] = rsqrtf(1.0f + (float)c);
    }
    if (t == 0 && lt == 0)
        g_offs[g * (N_NODES + 1) + N_NODES] = N_EDGES;
}

__global__ void k_fill2(const int* __restrict__ src1, const int* __restrict__ dst1,
                        const int* __restrict__ src2, const int* __restrict__ dst2) {
    const int Q = N_EDGES / 4;
    int i = blockIdx.x * blockDim.x + threadIdx.x;
    int stride = gridDim.x * blockDim.x;
    for (; i < 2 * Q; i += stride) {
        int4 s, d;
        int nbase, ebase;
        if (i < Q) {
            s = __ldg((const int4*)src1 + i);
            d = __ldg((const int4*)dst1 + i);
            nbase = 0; ebase = 0;
        } else {
            s = __ldg((const int4*)src2 + (i - Q));
            d = __ldg((const int4*)dst2 + (i - Q));
            nbase = N_NODES; ebase = N_EDGES;
        }
        g_csr[ebase + atomicAdd(&g_cur[nbase + d.x], 1)] = s.x;
        g_csr[ebase + atomicAdd(&g_cur[nbase + d.y], 1)] = s.y;
        g_csr[ebase + atomicAdd(&g_cur[nbase + d.z], 1)] = s.z;
        g_csr[ebase + atomicAdd(&g_cur[nbase + d.w], 1)] = s.w;
    }
}

// ---------------------------------------------------------------------------
// GEMM (fp16 HMMA m16n8k16; ldmatrix A; C restaged through smem -> STG.128).
// hs[m][:] = (x[m][:] @ W) * rsqrt(1+cnt[m]). fp16 output.
// Templated input: float (layer 1: cvt at fill) or __half (layer 2: copy).
// smem: A 32KB (reused for C restage) + B 16KB = 48KB; 2 CTAs/SM.
// ---------------------------------------------------------------------------
template<typename T>
__global__ __launch_bounds__(256, 2)
void k_gemm_h16(const T* __restrict__ xA, const T* __restrict__ xB,
                const uint4* __restrict__ Bq, const int* __restrict__ cntAB,
                __half* __restrict__ hsA, __half* __restrict__ hsB) {
    __shared__ uint4 As[2048];   // 128 rows x 16 chunks (32KB); reused for C
    __shared__ uint4 Bs[1024];   // half of B (16KB)

    const int tid  = threadIdx.x;
    const int lane = tid & 31;
    const int wid  = tid >> 5;
    const int g    = lane >> 2;
    const int l4   = lane & 3;
    const int wm   = (wid & 3) * 32;
    const int wnh  = wid >> 2;

    const int gph  = (blockIdx.x >= NBLK) ? 1 : 0;
    const int m0   = (blockIdx.x - gph * NBLK) * GM;
    const T* x     = gph ? xB : xA;
    __half* hs     = gph ? hsB : hsA;
    const int* cnt = cntAB + gph * N_NODES;

    // ---- Fill A tile (once, swizzled) ----
#pragma unroll
    for (int i = 0; i < 8; i++) {
        int f = i * 256 + tid;
        int r = f >> 4;
        int c = f & 15;
        int R = m0 + r;
        uint4 v = make_uint4(0u, 0u, 0u, 0u);
        if (R < N_NODES) {
            if constexpr (sizeof(T) == 4) {
                const float4* p = (const float4*)((const float*)x + (size_t)R * 128 + c * 8);
                float4 v0 = __ldg(p);
                float4 v1 = __ldg(p + 1);
                v.x = pack_h2(v0.x, v0.y);
                v.y = pack_h2(v0.z, v0.w);
                v.z = pack_h2(v1.x, v1.y);
                v.w = pack_h2(v1.z, v1.w);
            } else {
                v = __ldg((const uint4*)((const __half*)x + (size_t)R * 128) + c);
            }
        }
        As[r * 16 + (c ^ (r & 7))] = v;
    }

    const unsigned sA = (unsigned)__cvta_generic_to_shared(As);
    const int rloc  = wm + (lane & 7) + 8 * ((lane >> 3) & 1);
    const int cadd  = lane >> 4;
    const int rmask = lane & 7;
    const unsigned aoff0 = sA + (unsigned)(rloc * 256);
    const unsigned aoff1 = aoff0 + 16 * 256;

    float c[2][8][4];
#pragma unroll
    for (int mf = 0; mf < 2; mf++)
#pragma unroll
        for (int nb = 0; nb < 8; nb++)
#pragma unroll
            for (int q = 0; q < 4; q++) c[mf][nb][q] = 0.0f;

#pragma unroll
    for (int kc2 = 0; kc2 < 2; kc2++) {
        if (kc2) __syncthreads();
#pragma unroll
        for (int j = 0; j < 4; j++)
            Bs[tid + j * 256] = __ldg(Bq + kc2 * 1024 + tid + j * 256);
        __syncthreads();

#pragma unroll
        for (int kl = 0; kl < 2; kl++) {
#pragma unroll
            for (int ks = 0; ks < 2; ks++) {
                int c0 = (kc2 * 2 + kl) * 4 + ks * 2;
                unsigned sw = (unsigned)(((c0 + cadd) ^ rmask) << 4);
                unsigned a0[4], a1[4];
                ldsm_x4(a0, aoff0 + sw);
                ldsm_x4(a1, aoff1 + sw);
#pragma unroll
                for (int nbp = 0; nbp < 4; nbp++) {
                    uint4 bb = Bs[(((kl * 2 + ks) * 2 + wnh) * 4 + nbp) * 32 + lane];
                    mma16(c[0][2 * nbp],     a0, bb.x, bb.y);
                    mma16(c[0][2 * nbp + 1], a0, bb.z, bb.w);
                    mma16(c[1][2 * nbp],     a1, bb.x, bb.y);
                    mma16(c[1][2 * nbp + 1], a1, bb.z, bb.w);
                }
            }
        }
    }

    // ---- Epilogue: restage C through smem (reuse As), then coalesced STG ----
    __syncthreads();                     // all warps done reading As
    __half* Eh = (__half*)As;
#pragma unroll
    for (int mf = 0; mf < 2; mf++) {
        int r0 = wm + mf * 16 + g;       // local rows
        int r1 = r0 + 8;
        int Ra = m0 + r0, Rb = m0 + r1;
        float d0 = (Ra < N_NODES) ? rsqrtf(1.0f + (float)__ldg(cnt + Ra)) : 0.f;
        float d1 = (Rb < N_NODES) ? rsqrtf(1.0f + (float)__ldg(cnt + Rb)) : 0.f;
#pragma unroll
        for (int nb = 0; nb < 8; nb++) {
            int ch = wnh * 8 + nb;       // 16B chunk index of col
            __half2 o0 = __floats2half2_rn(c[mf][nb][0] * d0, c[mf][nb][1] * d0);
            __half2 o1 = __floats2half2_rn(c[mf][nb][2] * d1, c[mf][nb][3] * d1);
            *(__half2*)&Eh[r0 * 128 + ((ch ^ (r0 & 7)) << 3) + 2 * l4] = o0;
            *(__half2*)&Eh[r1 * 128 + ((ch ^ (r1 & 7)) << 3) + 2 * l4] = o1;
        }
    }
    __syncthreads();
#pragma unroll
    for (int j = 0; j < 8; j++) {
        int idx = j * 256 + tid;
        int r = idx >> 4, cl = idx & 15;
        int R = m0 + r;
        if (R < N_NODES)
            *((uint4*)(hs + (size_t)R * 128) + cl) = As[r * 16 + (cl ^ (r & 7))];
    }
}

// ---------------------------------------------------------------------------
// Aggregate + finalize v4: EIGHTH-WARP per node (4 lanes x 4 uint4 = 256B).
// 8 independent node chains per warp slot. 2 accumulator chain-sets (A/B).
// out[n] = dinv[n] * (sum_e hs[src_e] + hs[n]) + b   (+ ReLU)
// MID=true : out fp16 + ReLU (hidden). MID=false: out fp32, no ReLU.
// ---------------------------------------------------------------------------
__device__ __forceinline__ float4 h4tof4u(unsigned lo, unsigned hi) {
    float2 a = __half22float2(*(const __half2*)&lo);
    float2 b = __half22float2(*(const __half2*)&hi);
    return make_float4(a.x, a.y, b.x, b.y);
}
__device__ __forceinline__ void acc2(float4& X, float4& Y, uint4 v) {
    float4 l = h4tof4u(v.x, v.y);
    float4 h = h4tof4u(v.z, v.w);
    X.x += l.x; X.y += l.y; X.z += l.z; X.w += l.w;
    Y.x += h.x; Y.y += h.y; Y.z += h.z; Y.w += h.w;
}

template<bool MID>
__global__ __launch_bounds__(128)
void k_aggregate(const __half* __restrict__ hsA, const __half* __restrict__ hsB,
                 const float* __restrict__ b,
                 void* __restrict__ outA, void* __restrict__ outB) {
    int qid = blockIdx.x * 32 + (threadIdx.x >> 2);   // 4 lanes per node
    if (qid >= 2 * N_NODES) return;
    int gph  = (qid >= N_NODES) ? 1 : 0;
    int node = qid - gph * N_NODES;
    int h    = threadIdx.x & 3;                       // 64B quarter of the row

    const int*   offs = g_offs + gph * (N_NODES + 1);
    const int*   csr  = g_csr  + gph * N_EDGES;
    const uint4* hs4  = (const uint4*)(gph ? hsB : hsA);
    void* out = gph ? outB : outA;

    int beg = __ldg(offs + node);
    int end = __ldg(offs + node + 1);
    float dd = __ldg(g_dinv + qid);

    float4 A[8], B[8];
#pragma unroll
    for (int j = 0; j < 8; j++) {
        A[j] = make_float4(0.f, 0.f, 0.f, 0.f);
        B[j] = A[j];
    }

    const uint4* selfrow = hs4 + (size_t)node * 16 + h * 4;
    {
        uint4 v0 = __ldg(selfrow), v1 = __ldg(selfrow + 1);
        uint4 v2 = __ldg(selfrow + 2), v3 = __ldg(selfrow + 3);
        acc2(A[0], A[1], v0); acc2(A[2], A[3], v1);
        acc2(A[4], A[5], v2); acc2(A[6], A[7], v3);
    }

    int e = beg;
    while (e < end && (e & 3)) {
        const uint4* row = hs4 + (size_t)__ldg(csr + e) * 16 + h * 4;
        uint4 v0 = __ldg(row), v1 = __ldg(row + 1);
        uint4 v2 = __ldg(row + 2), v3 = __ldg(row + 3);
        acc2(B[0], B[1], v0); acc2(B[2], B[3], v1);
        acc2(B[4], B[5], v2); acc2(B[6], B[7], v3);
        e++;
    }
    for (; e + 4 <= end; e += 4) {
        int4 s = __ldg((const int4*)(csr + e));
        const uint4* r0 = hs4 + (size_t)s.x * 16 + h * 4;
        const uint4* r1 = hs4 + (size_t)s.y * 16 + h * 4;
        uint4 u0 = __ldg(r0),     u1 = __ldg(r0 + 1);
        uint4 u2 = __ldg(r0 + 2), u3 = __ldg(r0 + 3);
        uint4 w0 = __ldg(r1),     w1 = __ldg(r1 + 1);
        uint4 w2 = __ldg(r1 + 2), w3 = __ldg(r1 + 3);
        acc2(A[0], A[1], u0); acc2(A[2], A[3], u1);
        acc2(A[4], A[5], u2); acc2(A[6], A[7], u3);
        acc2(B[0], B[1], w0); acc2(B[2], B[3], w1);
        acc2(B[4], B[5], w2); acc2(B[6], B[7], w3);
        const uint4* r2 = hs4 + (size_t)s.z * 16 + h * 4;
        const uint4* r3 = hs4 + (size_t)s.w * 16 + h * 4;
        u0 = __ldg(r2); u1 = __ldg(r2 + 1); u2 = __ldg(r2 + 2); u3 = __ldg(r2 + 3);
        w0 = __ldg(r3); w1 = __ldg(r3 + 1); w2 = __ldg(r3 + 2); w3 = __ldg(r3 + 3);
        acc2(A[0], A[1], u0); acc2(A[2], A[3], u1);
        acc2(A[4], A[5], u2); acc2(A[6], A[7], u3);
        acc2(B[0], B[1], w0); acc2(B[2], B[3], w1);
        acc2(B[4], B[5], w2); acc2(B[6], B[7], w3);
    }
    for (; e < end; e++) {
        const uint4* row = hs4 + (size_t)__ldg(csr + e) * 16 + h * 4;
        uint4 v0 = __ldg(row), v1 = __ldg(row + 1);
        uint4 v2 = __ldg(row + 2), v3 = __ldg(row + 3);
        acc2(A[0], A[1], v0); acc2(A[2], A[3], v1);
        acc2(A[4], A[5], v2); acc2(A[6], A[7], v3);
    }

    const float4* b4 = (const float4*)b;
    float4 O[8];
#pragma unroll
    for (int j = 0; j < 8; j++) {
        float4 bb = __ldg(b4 + h * 8 + j);
        O[j].x = fmaf(A[j].x + B[j].x, dd, bb.x);
        O[j].y = fmaf(A[j].y + B[j].y, dd, bb.y);
        O[j].z = fmaf(A[j].z + B[j].z, dd, bb.z);
        O[j].w = fmaf(A[j].w + B[j].w, dd, bb.w);
        if (MID) {
            O[j].x = fmaxf(O[j].x, 0.f); O[j].y = fmaxf(O[j].y, 0.f);
            O[j].z = fmaxf(O[j].z, 0.f); O[j].w = fmaxf(O[j].w, 0.f);
        }
    }

    if (MID) {
        uint4* orow = (uint4*)out + (size_t)node * 16;
#pragma unroll
        for (int j = 0; j < 4; j++) {
            uint4 u;
            u.x = pack_h2(O[2 * j].x,     O[2 * j].y);
            u.y = pack_h2(O[2 * j].z,     O[2 * j].w);
            u.z = pack_h2(O[2 * j + 1].x, O[2 * j + 1].y);
            u.w = pack_h2(O[2 * j + 1].z, O[2 * j + 1].w);
            orow[h * 4 + j] = u;
        }
    } else {
        float4* orow = (float4*)out + (size_t)node * 32;
#pragma unroll
        for (int j = 0; j < 8; j++)
            orow[h * 8 + j] = O[j];
    }
}

// ---------------------------------------------------------------------------
// Launch. GEMM (layer 1) at launch index 3 for the ncu window.
// ---------------------------------------------------------------------------
extern "C" void kernel_launch(void* const* d_in, const int* in_sizes, int n_in,
                              void* d_out, int out_size) {
    const float* x1  = (const float*)d_in[0];
    const int*   ei1 = (const int*)  d_in[1];
    const float* x2  = (const float*)d_in[2];
    const int*   ei2 = (const int*)  d_in[3];
    const float* W0  = (const float*)d_in[4];
    const float* b0  = (const float*)d_in[5];
    const float* W1  = (const float*)d_in[6];
    const float* b1  = (const float*)d_in[7];
    float* out = (float*)d_out;

    const int* src1 = ei1;
    const int* dst1 = ei1 + N_EDGES;
    const int* src2 = ei2;
    const int* dst2 = ei2 + N_EDGES;

    __half *hsA, *hsB, *h16A, *h16B;
    uint4* Bq;
    int* cnt;
    cudaGetSymbolAddress((void**)&hsA,  g_hsA);
    cudaGetSymbolAddress((void**)&hsB,  g_hsB);
    cudaGetSymbolAddress((void**)&h16A, g_h16A);
    cudaGetSymbolAddress((void**)&h16B, g_h16B);
    cudaGetSymbolAddress((void**)&Bq,   g_Bq);
    cudaGetSymbolAddress((void**)&cnt,  g_cnt);

    k_packw_zero<<<(2 * N_NODES + 255) / 256, 256>>>(W0, W1);          // 0
    k_count2<<<1024, 256>>>(dst1, dst2);                               // 1
    k_blocksum<<<N_TILES, TILE>>>();                                   // 2
    k_gemm_h16<float><<<2 * NBLK, 256>>>(x1, x2, Bq, cnt, hsA, hsB);   // 3 (ncu)
    k_offsets<<<N_TILES, TILE>>>();                                    // 4
    k_fill2<<<1024, 256>>>(src1, dst1, src2, dst2);                    // 5

    const int AGG_GRID = (2 * N_NODES + 31) / 32;                      // 3125

    k_aggregate<true><<<AGG_GRID, 128>>>(hsA, hsB, b0, h16A, h16B);
    k_gemm_h16<__half><<<2 * NBLK, 256>>>(h16A, h16B, Bq + 2048, cnt, hsA, hsB);
    k_aggregate<false><<<AGG_GRID, 128>>>(hsA, hsB, b1, out, out + (size_t)N_NODES * DIM);
}